// round 12
// baseline (speedup 1.0000x reference)
#include <cuda_runtime.h>
#include <math.h>

#define BB 8
#define TT 2048
#define HH 1024
#define NCTA 128
#define NTHR 256
#define SHSTR 1040   // h row stride (floats); SHSTR/2 % 16 == 8 -> 2-phase LDS.64 floor
#define NGRP 8       // barrier counter groups (16 CTAs each)

typedef unsigned long long u64;

// ---------------- persistent scratch (device globals; zero-initialized) -----
__device__ float g_h[2][BB * HH];                 // double-buffered hidden state
__device__ u64 g_ctrs[NGRP * 16];                 // 8 counters, 128B apart

__device__ __forceinline__ void red_release_add(u64* p, u64 v) {
    asm volatile("red.release.gpu.global.add.u64 [%0], %1;" :: "l"(p), "l"(v) : "memory");
}
__device__ __forceinline__ u64 ld_acquire_u64(const u64* p) {
    u64 v;
    asm volatile("ld.acquire.gpu.global.u64 %0, [%1];" : "=l"(v) : "l"(p) : "memory");
    return v;
}
// packed fp32x2 FMA (Blackwell)
__device__ __forceinline__ u64 fma2(u64 a, u64 b, u64 c) {
    u64 d;
    asm("fma.rn.f32x2 %0, %1, %2, %3;" : "=l"(d) : "l"(a), "l"(b), "l"(c));
    return d;
}
__device__ __forceinline__ float fold2(u64 v) {
    return __uint_as_float((unsigned)v) + __uint_as_float((unsigned)(v >> 32));
}
__device__ __forceinline__ float tanhapx(float x) {
    float y;
    asm("tanh.approx.f32 %0, %1;" : "=f"(y) : "f"(x));
    return y;
}
__device__ __forceinline__ float sigapx(float x) {
    return fmaf(0.5f, tanhapx(0.5f * x), 0.5f);
}
__device__ __forceinline__ void bar_named(int id, int nthr) {
    asm volatile("bar.sync %0, %1;" :: "r"(id), "r"(nthr) : "memory");
}

// ---------------- fused persistent GRU kernel --------------------------------
// 128 CTAs x 256 threads (8 warps). warp -> (p = wid&3, kh = wid>>2):
// col-pair {cta*8+2p, +1}, K-half kh. lane -> (b4 = lane>>3, ks8 = lane&7):
// covers batches {b4, b4+4}, k-pairs kp = kh*256 + ks8 + 8j.
//
// Per step t, each lane accumulates BOTH W_hh·h(t) (h from smem) and
// W_ih·x(t) (x straight from L2, coalesced). r/z gates share accumulators
// (x-part + h-part sum before the activation); n-gate keeps x/h separate:
//   n = tanh( (x·Win + bih_n) + r * (h·Whn + bhh_n) ).
// Both W matrices SMEM-resident for the whole run (96 KB each, packed so 6
// values per k-pair come from 3 dense 1-phase LDS.128 per matrix).
// Grid barrier: 8 split release-add counters (16 CTAs each), monotonic.
__global__ void __launch_bounds__(NTHR, 1) gru_fused_kernel(
    const float* __restrict__ x,     // [B, T, H]
    const float* __restrict__ Wih,   // [3H, H]
    const float* __restrict__ bih,   // [3H]
    const float* __restrict__ Whh,   // [3H, H]
    const float* __restrict__ bhh,   // [3H]
    float* __restrict__ out)         // [B, T, H]
{
    extern __shared__ float smem[];
    u64*   sWh  = (u64*)smem;                    // [4][512][6] u64 = 96KB
    u64*   sWi  = sWh + 4 * 512 * 6;             // [4][512][6] u64 = 96KB
    float* sh   = (float*)(sWi + 4 * 512 * 6);   // [8][SHSTR]  32.5KB
    float* sRed = sh + BB * SHSTR;               // [8 warps][4 b4][16] = 2KB

    const int tid  = threadIdx.x;
    const int cta  = blockIdx.x;
    const int wid  = tid >> 5;
    const int lane = tid & 31;
    const int p    = wid & 3;
    const int kh   = wid >> 2;        // K-half 0/1
    const int b4   = lane >> 3;       // 0..3
    const int ks8  = lane & 7;        // 0..7
    const int gtid = tid & 127;       // id within half-group
    const int grp  = cta >> 4;        // counter group 0..7

    // ---- pack W_hh AND W_ih: s[((pp*512 + kp)*6) + jloc*3 + g] ----
    for (int idx = tid; idx < 24 * 512; idx += NTHR) {
        int row = idx >> 9;
        int kp  = idx & 511;
        int jglob = row / 3;
        int g     = row % 3;
        int pp    = jglob >> 1;
        int jloc  = jglob & 1;
        size_t off = (size_t)(g * HH + cta * 8 + jglob) * HH + kp * 2;
        int dst = ((pp * 512 + kp) * 6) + jloc * 3 + g;
        sWh[dst] = *(const u64*)(Whh + off);
        sWi[dst] = *(const u64*)(Wih + off);
    }
    __syncthreads();

    const int c0 = cta * 8 + 2 * p;
    // finalize-lane biases: r/z combined (bih+bhh); n split (bin = bih_n, bhn = bhh_n)
    float br[2], bz[2], bin[2], bhn[2];
#pragma unroll
    for (int jl = 0; jl < 2; ++jl) {
        int c = c0 + jl;
        br[jl]  = bih[c] + bhh[c];
        bz[jl]  = bih[HH + c] + bhh[HH + c];
        bin[jl] = bih[2 * HH + c];
        bhn[jl] = bhh[2 * HH + c];
    }

    const u64* whbase = sWh + (size_t)p * 512 * 6;
    const u64* wibase = sWi + (size_t)p * 512 * 6;
    const float* hrowA = sh + b4 * SHSTR;          // batch b4
    const float* hrowB = sh + (b4 + 4) * SHSTR;    // batch b4+4
    const float* xpA = x + (size_t)b4 * TT * HH;         // advance by HH per step
    const float* xpB = x + (size_t)(b4 + 4) * TT * HH;

    // poller base per counter (monotonic; exact floor at launch boundaries)
    const bool poller = (lane < 8) && (wid == 0 || wid == 4);
    u64 mybase = 0;
    if (poller) {
        u64 craw = ld_acquire_u64(&g_ctrs[lane * 16]);
        mybase = craw - (craw % (u64)(16 * TT));
    }

    // previous-h registers for this finalize lane's own columns
    float hp0 = 0.f, hp1 = 0.f;
    const int fb = lane & 7;          // finalize batch for kh0 lanes<8

    for (int t = 0; t < TT; ++t) {
        // ---- stage this group's K-half of h(t) into smem ----
        if (t == 0) {
            float4 z4 = make_float4(0.f, 0.f, 0.f, 0.f);
#pragma unroll
            for (int i = 0; i < 8; ++i) {
                int lin = gtid + i * 128;
                int bb  = lin >> 7;
                int k4  = (lin & 127) + kh * 128;
                ((float4*)(sh + bb * SHSTR))[k4] = z4;
            }
        } else {
            const float* hin = g_h[t & 1];
#pragma unroll
            for (int i = 0; i < 8; ++i) {
                int lin = gtid + i * 128;
                int bb  = lin >> 7;
                int k4  = (lin & 127) + kh * 128;
                ((float4*)(sh + bb * SHSTR))[k4] =
                    __ldcg(((const float4*)(hin + (size_t)bb * HH)) + k4);
            }
        }

        bar_named(1 + kh, 128);   // own half staged -> group computes

        // ---- fused dot products over this warp's K-half ----
        // acc index: [batch A/B][jl][q], q: r (x+h merged), z (merged), hn, xn
        u64 aA0r = 0ull, aA0z = 0ull, aA0hn = 0ull, aA0xn = 0ull;
        u64 aA1r = 0ull, aA1z = 0ull, aA1hn = 0ull, aA1xn = 0ull;
        u64 aB0r = 0ull, aB0z = 0ull, aB0hn = 0ull, aB0xn = 0ull;
        u64 aB1r = 0ull, aB1z = 0ull, aB1hn = 0ull, aB1xn = 0ull;
        const int kp0 = kh * 256 + ks8;
#pragma unroll 4
        for (int j = 0; j < 32; ++j) {
            int kp = kp0 + j * 8;
            const u64* wp = whbase + (size_t)kp * 6;
            const u64* ip = wibase + (size_t)kp * 6;
            ulonglong2 wA = *(const ulonglong2*)(wp + 0);   // (jl0,r) (jl0,z)
            ulonglong2 wB = *(const ulonglong2*)(wp + 2);   // (jl0,n) (jl1,r)
            ulonglong2 wC = *(const ulonglong2*)(wp + 4);   // (jl1,z) (jl1,n)
            ulonglong2 iA = *(const ulonglong2*)(ip + 0);
            ulonglong2 iB = *(const ulonglong2*)(ip + 2);
            ulonglong2 iC = *(const ulonglong2*)(ip + 4);
            u64 hA = *(const u64*)(hrowA + 2 * kp);
            u64 hB = *(const u64*)(hrowB + 2 * kp);
            u64 xA = __ldg((const u64*)(xpA + 2 * kp));
            u64 xB = __ldg((const u64*)(xpB + 2 * kp));

            aA0r  = fma2(wA.x, hA, aA0r);   aA0r  = fma2(iA.x, xA, aA0r);
            aA0z  = fma2(wA.y, hA, aA0z);   aA0z  = fma2(iA.y, xA, aA0z);
            aA0hn = fma2(wB.x, hA, aA0hn);  aA0xn = fma2(iB.x, xA, aA0xn);
            aA1r  = fma2(wB.y, hA, aA1r);   aA1r  = fma2(iB.y, xA, aA1r);
            aA1z  = fma2(wC.x, hA, aA1z);   aA1z  = fma2(iC.x, xA, aA1z);
            aA1hn = fma2(wC.y, hA, aA1hn);  aA1xn = fma2(iC.y, xA, aA1xn);

            aB0r  = fma2(wA.x, hB, aB0r);   aB0r  = fma2(iA.x, xB, aB0r);
            aB0z  = fma2(wA.y, hB, aB0z);   aB0z  = fma2(iA.y, xB, aB0z);
            aB0hn = fma2(wB.x, hB, aB0hn);  aB0xn = fma2(iB.x, xB, aB0xn);
            aB1r  = fma2(wB.y, hB, aB1r);   aB1r  = fma2(iB.y, xB, aB1r);
            aB1z  = fma2(wC.x, hB, aB1z);   aB1z  = fma2(iC.x, xB, aB1z);
            aB1hn = fma2(wC.y, hB, aB1hn);  aB1xn = fma2(iC.y, xB, aB1xn);
        }

        // fold + reduce over ks8 (shfl within 8-lane groups)
        float s[16];
        s[0]  = fold2(aA0r);  s[1]  = fold2(aA0z);
        s[2]  = fold2(aA0hn); s[3]  = fold2(aA0xn);
        s[4]  = fold2(aA1r);  s[5]  = fold2(aA1z);
        s[6]  = fold2(aA1hn); s[7]  = fold2(aA1xn);
        s[8]  = fold2(aB0r);  s[9]  = fold2(aB0z);
        s[10] = fold2(aB0hn); s[11] = fold2(aB0xn);
        s[12] = fold2(aB1r);  s[13] = fold2(aB1z);
        s[14] = fold2(aB1hn); s[15] = fold2(aB1xn);
#pragma unroll
        for (int off = 1; off <= 4; off <<= 1) {
#pragma unroll
            for (int i = 0; i < 16; ++i)
                s[i] += __shfl_xor_sync(0xffffffffu, s[i], off);
        }

        if (ks8 == 0) {
            float* dst = sRed + ((wid * 4 + b4) * 16);
#pragma unroll
            for (int i = 0; i < 16; ++i) dst[i] = s[i];
        }
        __syncthreads();   // all compute + sRed done; sh is dead

        if (kh == 0) {
            if (lane < 8) {
                const int rb4  = fb & 3;
                const int off8 = (fb >> 2) * 8;   // batch-half select
                const float* r0 = sRed + ((p * 4 + rb4) * 16) + off8;
                const float* r1 = sRed + (((4 + p) * 4 + rb4) * 16) + off8;
                float gsum[8];
#pragma unroll
                for (int i = 0; i < 8; ++i) gsum[i] = r0[i] + r1[i];

                // per col jl: gsum[jl*4 + {0:r,1:z,2:hn,3:xn}]
                float rr0 = sigapx(gsum[0] + br[0]);
                float zz0 = sigapx(gsum[1] + bz[0]);
                float nn0 = tanhapx(gsum[3] + bin[0] + rr0 * (gsum[2] + bhn[0]));
                float rr1 = sigapx(gsum[4] + br[1]);
                float zz1 = sigapx(gsum[5] + bz[1]);
                float nn1 = tanhapx(gsum[7] + bin[1] + rr1 * (gsum[6] + bhn[1]));
                float h0 = (1.0f - zz0) * nn0 + zz0 * hp0;
                float h1 = (1.0f - zz1) * nn1 + zz1 * hp1;
                hp0 = h0; hp1 = h1;

                *(float2*)(out + ((size_t)fb * TT + t) * HH + c0) = make_float2(h0, h1);
                float* hnext = g_h[(t + 1) & 1] + (size_t)fb * HH + c0;
                asm volatile("st.global.cg.v2.f32 [%0], {%1, %2};"
                             :: "l"(hnext), "f"(h0), "f"(h1) : "memory");
            }
            bar_named(3, 128);      // orders h stores before the release-add
            if (tid == 0) red_release_add(&g_ctrs[grp * 16], 1ull);
            if (wid == 0 && lane < 8) {
                const u64 tgt = mybase + (u64)16 * (u64)(t + 1);
                while (ld_acquire_u64(&g_ctrs[lane * 16]) < tgt) { }
            }
            bar_named(3, 128);      // poll result -> whole kh0 group
        } else {
            if (wid == 4 && lane < 8) {
                const u64 tgt = mybase + (u64)16 * (u64)(t + 1);
                while (ld_acquire_u64(&g_ctrs[lane * 16]) < tgt) { }
            }
            bar_named(4, 128);      // poll result -> whole kh1 group
        }

        xpA += HH;
        xpB += HH;
    }
    // counters end at base + 16*TT (multiple of 16*TT) -> replay-safe
}

// ---------------- launcher ---------------------------------------------------
extern "C" void kernel_launch(void* const* d_in, const int* in_sizes, int n_in,
                              void* d_out, int out_size) {
    const float* x   = (const float*)d_in[0];
    const float* Wih = (const float*)d_in[1];
    const float* bih = (const float*)d_in[2];
    const float* Whh = (const float*)d_in[3];
    const float* bhh = (const float*)d_in[4];
    float* out = (float*)d_out;

    (void)in_sizes; (void)n_in; (void)out_size;

    // smem: 2x W pack 96KB + h stage 32.5KB + reduce 2KB = 231,936 B
    const int kSmem = 2 * (4 * 512 * 6) * 8 + (BB * SHSTR) * 4 + (8 * 4 * 16) * 4;
    cudaFuncSetAttribute(gru_fused_kernel,
                         cudaFuncAttributeMaxDynamicSharedMemorySize, kSmem);

    gru_fused_kernel<<<NCTA, NTHR, kSmem>>>(x, Wih, bih, Whh, bhh, out);
}

// round 17
// speedup vs baseline: 1.5243x; 1.5243x over previous
#include <cuda_runtime.h>
#include <math.h>

#define BB 8
#define TT 2048
#define HH 1024
#define G3 3072
#define NCTA 128
#define NTHR 384          // warps 0-3: GEMM; warps 4-11: recurrence
#define SHSTR 1040        // h row stride (floats); 2-phase LDS.64 floor
#define NGRP 8            // barrier counter groups (16 CTAs each)
#define NTAU 32           // 2048/64 timestep blocks
#define TPT 384           // tiles per tau (8 batch-blocks x 48 n-blocks)
#define NTILES (NTAU * TPT)
#define SPAD 18

typedef unsigned long long u64;

// ---------------- persistent scratch (device globals; zero-initialized) -----
__device__ float g_xproj[(size_t)TT * BB * G3];   // [t][b][3H]
__device__ float g_h[2][BB * HH];                 // double-buffered hidden state
__device__ u64 g_ctrs[NGRP * 16];                 // grid-barrier counters, 128B apart
__device__ u64 g_prog[NTAU * 16];                 // xproj progress per tau, 128B apart

__device__ __forceinline__ void red_release_add(u64* p, u64 v) {
    asm volatile("red.release.gpu.global.add.u64 [%0], %1;" :: "l"(p), "l"(v) : "memory");
}
__device__ __forceinline__ u64 ld_acquire_u64(const u64* p) {
    u64 v;
    asm volatile("ld.acquire.gpu.global.u64 %0, [%1];" : "=l"(v) : "l"(p) : "memory");
    return v;
}
__device__ __forceinline__ u64 fma2(u64 a, u64 b, u64 c) {
    u64 d;
    asm("fma.rn.f32x2 %0, %1, %2, %3;" : "=l"(d) : "l"(a), "l"(b), "l"(c));
    return d;
}
__device__ __forceinline__ float fold2(u64 v) {
    return __uint_as_float((unsigned)v) + __uint_as_float((unsigned)(v >> 32));
}
__device__ __forceinline__ float tanhapx(float x) {
    float y;
    asm("tanh.approx.f32 %0, %1;" : "=f"(y) : "f"(x));
    return y;
}
__device__ __forceinline__ float sigapx(float x) {
    return fmaf(0.5f, tanhapx(0.5f * x), 0.5f);
}
__device__ __forceinline__ void bar_named(int id, int nthr) {
    asm volatile("bar.sync %0, %1;" :: "r"(id), "r"(nthr) : "memory");
}

// ---------------- fused mega-kernel ------------------------------------------
// SMEM (floats): sWp[24576] | sh[8*SHSTR] | sRed[384] | As[1152] | Bs[1152]
__global__ void __launch_bounds__(NTHR, 1) gru_mega_kernel(
    const float* __restrict__ x,     // [B, T, H]
    const float* __restrict__ Wih,   // [3H, H]
    const float* __restrict__ bih,   // [3H]
    const float* __restrict__ Whh,   // [3H, H]
    const float* __restrict__ bhh,   // [3H]
    float* __restrict__ out)         // [B, T, H]
{
    extern __shared__ float smem[];
    u64*   sWp  = (u64*)smem;                    // [4][512][6] u64 = 96KB
    float* sh   = smem + 24576;                  // [8][SHSTR]
    float* sRed = sh + BB * SHSTR;               // [8 warps][4 b4][12]
    float* As   = sRed + 8 * 4 * 12;             // [64][SPAD]
    float* Bs   = As + 64 * SPAD;                // [64][SPAD]

    const int tid  = threadIdx.x;
    const int cta  = blockIdx.x;
    const int wid  = tid >> 5;
    const int lane = tid & 31;

    // ---- pack W_hh (all 384 threads): sWp[((pp*512+kp)*6) + jloc*3 + g] ----
    for (int idx = tid; idx < 24 * 512; idx += NTHR) {
        int row = idx >> 9;
        int kp  = idx & 511;
        int jglob = row / 3;
        int g     = row % 3;
        int pp    = jglob >> 1;
        int jloc  = jglob & 1;
        const float* src = Whh + (size_t)(g * HH + cta * 8 + jglob) * HH + kp * 2;
        sWp[((pp * 512 + kp) * 6) + jloc * 3 + g] = *(const u64*)src;
    }
    __syncthreads();   // the ONLY all-384 barrier

    // =========================== GEMM warps (wid 0-3) ========================
    if (wid < 4) {
        const int gt = tid;               // 0..127
        const int tx = gt & 7;            // cols tx + 8u, u<8
        const int ty = gt >> 3;           // rows ty*4 .. ty*4+3
        const int ldRow = gt >> 1;        // 0..63
        const int ldCol = (gt & 1) * 8;   // 0 or 8

        for (int i = 0; i < 96; ++i) {
            const int tile = cta + NCTA * i;      // tau-major global order
            const int tau  = tile / TPT;
            const int rem  = tile % TPT;
            const int bb   = rem / 48;
            const int nb   = rem % 48;
            const int m0   = bb * TT + tau * 64;  // x row = b*T + t
            const int n0   = nb * 64;

            const float* aPtr = x   + (size_t)(m0 + ldRow) * HH + ldCol;
            const float* bPtr = Wih + (size_t)(n0 + ldRow) * HH + ldCol;

            u64 acc[4][8];
#pragma unroll
            for (int r = 0; r < 4; ++r)
#pragma unroll
                for (int u = 0; u < 8; ++u) acc[r][u] = 0ull;

            for (int k0 = 0; k0 < HH; k0 += 16) {
                float4 a0 = __ldcs((const float4*)(aPtr + k0));
                float4 a1 = __ldcs((const float4*)(aPtr + k0 + 4));
                float4 b0 = *(const float4*)(bPtr + k0);
                float4 b1 = *(const float4*)(bPtr + k0 + 4);
                bar_named(6, 128);   // previous iteration's reads done
                *(float2*)&As[ldRow * SPAD + ldCol + 0] = make_float2(a0.x, a0.y);
                *(float2*)&As[ldRow * SPAD + ldCol + 2] = make_float2(a0.z, a0.w);
                *(float2*)&As[ldRow * SPAD + ldCol + 4] = make_float2(a1.x, a1.y);
                *(float2*)&As[ldRow * SPAD + ldCol + 6] = make_float2(a1.z, a1.w);
                *(float2*)&Bs[ldRow * SPAD + ldCol + 0] = make_float2(b0.x, b0.y);
                *(float2*)&Bs[ldRow * SPAD + ldCol + 2] = make_float2(b0.z, b0.w);
                *(float2*)&Bs[ldRow * SPAD + ldCol + 4] = make_float2(b1.x, b1.y);
                *(float2*)&Bs[ldRow * SPAD + ldCol + 6] = make_float2(b1.z, b1.w);
                bar_named(6, 128);   // tile staged

#pragma unroll
                for (int kk2 = 0; kk2 < 8; ++kk2) {
                    u64 a2[4], b2[8];
#pragma unroll
                    for (int r = 0; r < 4; ++r)
                        a2[r] = *(const u64*)&As[(ty * 4 + r) * SPAD + kk2 * 2];
#pragma unroll
                    for (int u = 0; u < 8; ++u)
                        b2[u] = *(const u64*)&Bs[(tx + 8 * u) * SPAD + kk2 * 2];
#pragma unroll
                    for (int r = 0; r < 4; ++r)
#pragma unroll
                        for (int u = 0; u < 8; ++u)
                            acc[r][u] = fma2(a2[r], b2[u], acc[r][u]);
                }
            }

            // epilogue: scatter to [t][b][3H]
#pragma unroll
            for (int r = 0; r < 4; ++r) {
                int trow = tau * 64 + ty * 4 + r;
                float* orow = g_xproj + ((size_t)trow * BB + bb) * G3 + n0;
#pragma unroll
                for (int u = 0; u < 8; ++u) {
                    int c = tx + 8 * u;
                    orow[c] = fold2(acc[r][u]) + __ldg(bih + n0 + c);
                }
            }
            bar_named(6, 128);   // all stores of this tile issued & warp-synced
            if (gt == 0) red_release_add(&g_prog[tau * 16], 1ull);
        }
        return;   // GEMM warps exit; recurrence keeps the SM
    }

    // ======================== recurrence warps (wid 4-11) ====================
    const int rwid = wid - 4;          // 0..7
    const int rtid = tid - 128;        // 0..255
    const int p    = rwid & 3;
    const int kh   = rwid >> 2;        // K-half 0/1
    const int b4   = lane >> 3;        // 0..3
    const int ks8  = lane & 7;         // 0..7
    const int gtid = rtid & 127;       // id within half-group
    const int grp  = cta >> 4;         // counter group 0..7

    const int c0 = cta * 8 + 2 * p;
    float bh[6];
#pragma unroll
    for (int jl = 0; jl < 2; ++jl)
#pragma unroll
        for (int g = 0; g < 3; ++g)
            bh[jl * 3 + g] = bhh[g * HH + c0 + jl];

    const u64* wbase = sWp + (size_t)p * 512 * 6;
    const float* hrowA = sh + b4 * SHSTR;          // batch b4
    const float* hrowB = sh + (b4 + 4) * SHSTR;    // batch b4+4

    // barrier base (monotonic counters; exact floor at launch boundaries)
    const bool poller = (lane < 8) && (rwid == 0 || rwid == 4);
    u64 mybase = 0;
    if (poller) {
        u64 craw = ld_acquire_u64(&g_ctrs[lane * 16]);
        mybase = craw - (craw % (u64)(16 * TT));
    }
    // xproj progress base: all tau counters share the same per-run history
    // (+TPT each); read early (<< one tile latency) so the floor is exact.
    u64 pbase = 0;
    if (kh == 0 && lane < 8) {
        u64 praw = ld_acquire_u64(&g_prog[0]);
        pbase = praw - (praw % (u64)TPT);
    }

    float hp0 = 0.f, hp1 = 0.f;        // prev h for this finalize lane's cols
    const int fb = lane & 7;           // finalize batch for kh0 lanes<8
    int tau_ok = -1;

    // step-0 xproj prefetch (gated on tau 0)
    float xv[6];
    if (kh == 0 && lane < 8) {
        while (ld_acquire_u64(&g_prog[0]) < pbase + (u64)TPT) { }
        tau_ok = 0;
        const float* px = g_xproj + (size_t)fb * G3;   // t=0
#pragma unroll
        for (int g = 0; g < 3; ++g) {
            float2 v = *(const float2*)(px + g * HH + c0);
            xv[0 * 3 + g] = v.x;
            xv[1 * 3 + g] = v.y;
        }
    }

    for (int t = 0; t < TT; ++t) {
        // ---- stage this group's K-half of h(t) into smem ----
        if (t == 0) {
            float4 z4 = make_float4(0.f, 0.f, 0.f, 0.f);
#pragma unroll
            for (int i = 0; i < 8; ++i) {
                int lin = gtid + i * 128;
                int bb  = lin >> 7;
                int k4  = (lin & 127) + kh * 128;
                ((float4*)(sh + bb * SHSTR))[k4] = z4;
            }
        } else {
            const float* hin = g_h[t & 1];
#pragma unroll
            for (int i = 0; i < 8; ++i) {
                int lin = gtid + i * 128;
                int bb  = lin >> 7;
                int k4  = (lin & 127) + kh * 128;
                ((float4*)(sh + bb * SHSTR))[k4] =
                    __ldcg(((const float4*)(hin + (size_t)bb * HH)) + k4);
            }
        }

        // prefetch next step's xproj (gated per 64-step tau block)
        float xnx[6] = {0.f, 0.f, 0.f, 0.f, 0.f, 0.f};
        if (kh == 0 && lane < 8 && t + 1 < TT) {
            int tau = (t + 1) >> 6;
            if (tau != tau_ok) {
                while (ld_acquire_u64(&g_prog[tau * 16]) < pbase + (u64)TPT) { }
                tau_ok = tau;
            }
            const float* px = g_xproj + ((size_t)(t + 1) * BB + fb) * G3;
#pragma unroll
            for (int g = 0; g < 3; ++g) {
                float2 v = *(const float2*)(px + g * HH + c0);
                xnx[0 * 3 + g] = v.x;
                xnx[1 * 3 + g] = v.y;
            }
        }

        bar_named(1 + kh, 128);   // own half staged -> group computes

        // ---- partial dot products: 6 (jloc x gate) x 2 batches ----
        u64 aA0 = 0ull, aA1 = 0ull, aA2 = 0ull, aA3 = 0ull, aA4 = 0ull, aA5 = 0ull;
        u64 aB0 = 0ull, aB1 = 0ull, aB2 = 0ull, aB3 = 0ull, aB4 = 0ull, aB5 = 0ull;
        const int kp0 = kh * 256 + ks8;
#pragma unroll 4
        for (int j = 0; j < 32; ++j) {
            int kp = kp0 + j * 8;
            const u64* wp = wbase + (size_t)kp * 6;
            ulonglong2 wA = *(const ulonglong2*)(wp + 0);   // jl0g0, jl0g1
            ulonglong2 wB = *(const ulonglong2*)(wp + 2);   // jl0g2, jl1g0
            ulonglong2 wC = *(const ulonglong2*)(wp + 4);   // jl1g1, jl1g2
            u64 hA = *(const u64*)(hrowA + 2 * kp);
            u64 hB = *(const u64*)(hrowB + 2 * kp);
            aA0 = fma2(wA.x, hA, aA0);  aB0 = fma2(wA.x, hB, aB0);
            aA1 = fma2(wA.y, hA, aA1);  aB1 = fma2(wA.y, hB, aB1);
            aA2 = fma2(wB.x, hA, aA2);  aB2 = fma2(wB.x, hB, aB2);
            aA3 = fma2(wB.y, hA, aA3);  aB3 = fma2(wB.y, hB, aB3);
            aA4 = fma2(wC.x, hA, aA4);  aB4 = fma2(wC.x, hB, aB4);
            aA5 = fma2(wC.y, hA, aA5);  aB5 = fma2(wC.y, hB, aB5);
        }

        // fold + reduce over ks8 (shfl within 8-lane groups)
        float s[12];
        s[0] = fold2(aA0); s[1] = fold2(aA1); s[2]  = fold2(aA2);
        s[3] = fold2(aA3); s[4] = fold2(aA4); s[5]  = fold2(aA5);
        s[6] = fold2(aB0); s[7] = fold2(aB1); s[8]  = fold2(aB2);
        s[9] = fold2(aB3); s[10] = fold2(aB4); s[11] = fold2(aB5);
#pragma unroll
        for (int off = 1; off <= 4; off <<= 1) {
#pragma unroll
            for (int i = 0; i < 12; ++i)
                s[i] += __shfl_xor_sync(0xffffffffu, s[i], off);
        }

        if (ks8 == 0) {
            float* dst = sRed + ((rwid * 4 + b4) * 12);
#pragma unroll
            for (int i = 0; i < 12; ++i) dst[i] = s[i];
        }
        bar_named(5, 256);   // both halves' sRed done; sh is dead

        if (kh == 0) {
            if (lane < 8) {
                const int rb4 = fb & 3;
                const int off6 = (fb >> 2) * 6;
                const float* r0 = sRed + ((p * 4 + rb4) * 12) + off6;
                const float* r1 = sRed + (((4 + p) * 4 + rb4) * 12) + off6;
                float gsum[6];
#pragma unroll
                for (int i = 0; i < 6; ++i) gsum[i] = r0[i] + r1[i];

                // order jloc*3+g; g: 0=r,1=z,2=n; bhh_n sits INSIDE the r* term
                float rr0 = sigapx(xv[0] + bh[0] + gsum[0]);
                float zz0 = sigapx(xv[1] + bh[1] + gsum[1]);
                float nn0 = tanhapx(xv[2] + rr0 * (gsum[2] + bh[2]));
                float rr1 = sigapx(xv[3] + bh[3] + gsum[3]);
                float zz1 = sigapx(xv[4] + bh[4] + gsum[4]);
                float nn1 = tanhapx(xv[5] + rr1 * (gsum[5] + bh[5]));
                float h0 = (1.0f - zz0) * nn0 + zz0 * hp0;
                float h1 = (1.0f - zz1) * nn1 + zz1 * hp1;
                hp0 = h0; hp1 = h1;

                *(float2*)(out + ((size_t)fb * TT + t) * HH + c0) = make_float2(h0, h1);
                float* hnext = g_h[(t + 1) & 1] + (size_t)fb * HH + c0;
                asm volatile("st.global.cg.v2.f32 [%0], {%1, %2};"
                             :: "l"(hnext), "f"(h0), "f"(h1) : "memory");
            }
            bar_named(3, 128);      // orders h stores before the release-add
            if (rtid == 0) red_release_add(&g_ctrs[grp * 16], 1ull);
            if (rwid == 0 && lane < 8) {
                const u64 tgt = mybase + (u64)16 * (u64)(t + 1);
                while (ld_acquire_u64(&g_ctrs[lane * 16]) < tgt) { }
            }
            bar_named(3, 128);      // poll result -> whole kh0 group
        } else {
            if (rwid == 4 && lane < 8) {
                const u64 tgt = mybase + (u64)16 * (u64)(t + 1);
                while (ld_acquire_u64(&g_ctrs[lane * 16]) < tgt) { }
            }
            bar_named(4, 128);      // poll result -> whole kh1 group
        }

#pragma unroll
        for (int i = 0; i < 6; ++i) xv[i] = xnx[i];
    }
    // g_ctrs end at base + 16*TT; g_prog at base + TPT per tau -> replay-safe
}

// ---------------- launcher ---------------------------------------------------
extern "C" void kernel_launch(void* const* d_in, const int* in_sizes, int n_in,
                              void* d_out, int out_size) {
    const float* x   = (const float*)d_in[0];
    const float* Wih = (const float*)d_in[1];
    const float* bih = (const float*)d_in[2];
    const float* Whh = (const float*)d_in[3];
    const float* bhh = (const float*)d_in[4];
    float* out = (float*)d_out;

    (void)in_sizes; (void)n_in; (void)out_size;

    // smem: W 96KB + h 32.5KB + red 1.5KB + As/Bs 9KB = 142,336 B
    const int kSmem = (24576 + BB * SHSTR + 8 * 4 * 12 + 2 * 64 * SPAD) * 4;
    cudaFuncSetAttribute(gru_mega_kernel,
                         cudaFuncAttributeMaxDynamicSharedMemorySize, kSmem);

    gru_mega_kernel<<<NCTA, NTHR, kSmem>>>(x, Wih, bih, Whh, bhh, out);
}